// round 4
// baseline (speedup 1.0000x reference)
#include <cuda_runtime.h>
#include <math.h>

#define BB   4096
#define NN   64
#define DD   256
#define OUTD 512
#define NIT  3

// Transposed weight scratch
__device__ float g_w1t[DD * OUTD];    // [256][512]
__device__ float g_w2t[OUTD * OUTD];  // [512][512]

// ---- packed f32x2 helpers (sm_100+) ----
#define FMA2(d, a, b) asm("fma.rn.f32x2 %0, %1, %2, %0;" : "+l"(d) : "l"(a), "l"(b))
#define DUP2(d, s)    asm("mov.b64 %0, {%1, %1};" : "=l"(d) : "r"(s))
#define UNPK2(lo, hi, d) asm("mov.b64 {%0, %1}, %2;" : "=r"(lo), "=r"(hi) : "l"(d))

// ---------------------------------------------------------------------------
// Tiled transpose: out[c][r] = in[r][c], in is [R][C]
// ---------------------------------------------------------------------------
__global__ void transpose_kernel(const float* __restrict__ in,
                                 float* __restrict__ out, int R, int C)
{
    __shared__ float tile[32][33];
    const int c0 = blockIdx.x * 32;
    const int r0 = blockIdx.y * 32;
    const int tx = threadIdx.x;
    const int ty = threadIdx.y;
    #pragma unroll
    for (int i = 0; i < 4; i++) {
        int r = r0 + ty + 8 * i;
        int c = c0 + tx;
        if (r < R && c < C) tile[ty + 8 * i][tx] = in[(size_t)r * C + c];
    }
    __syncthreads();
    #pragma unroll
    for (int i = 0; i < 4; i++) {
        int c = c0 + ty + 8 * i;
        int r = r0 + tx;
        if (r < R && c < C) out[(size_t)c * R + r] = tile[tx][ty + 8 * i];
    }
}

__device__ __forceinline__ float wsum(float v) {
    #pragma unroll
    for (int o = 16; o > 0; o >>= 1) v += __shfl_xor_sync(0xFFFFFFFFu, v, o);
    return v;
}

// ---------------------------------------------------------------------------
// Kernel 1: soft clustering. 512 threads, one batch per block.
// Warp w (0..15) owns rows 4w..4w+3.
// Lane l owns INTERLEAVED dims {l, l+32, ..., l+224} -> all smem traffic
// is conflict-free scalar. Softmax + ||mu|| computed redundantly per warp.
// ---------------------------------------------------------------------------
__global__ void __launch_bounds__(512, 2)
cluster_kernel(const float* __restrict__ h,
               const float* __restrict__ log_tau,
               float* __restrict__ out_alpha,   // [B, 64]
               float* __restrict__ out_mu)      // [B, 256]
{
    __shared__ float pmu[16][DD];    // per-warp partial mu (16KB)
    __shared__ float mu_s[DD];
    __shared__ float simv[NN];

    const int b = blockIdx.x;
    const int t = threadIdx.x;       // 0..511
    const int w = t >> 5;            // 0..15
    const int l = t & 31;

    const float* hb = h + (size_t)b * NN * DD;

    // --- load 4 rows x 8 interleaved dims (coalesced LDG.32) ---
    float hv[4][8];
    #pragma unroll
    for (int r = 0; r < 4; r++) {
        const float* p = hb + (size_t)(4 * w + r) * DD + l;
        #pragma unroll
        for (int j = 0; j < 8; j++)
            hv[r][j] = p[32 * j];
    }

    float tau = expf(log_tau[0]);
    tau = fminf(fmaxf(tau, 0.01f), 2.0f);
    const float inv_tau = 1.0f / tau;

    // --- per-row inverse norms, pre-multiplied by 1/tau ---
    float rni[4];
    #pragma unroll
    for (int r = 0; r < 4; r++) {
        float s = 0.0f;
        #pragma unroll
        for (int j = 0; j < 8; j++) s += hv[r][j] * hv[r][j];
        s = wsum(s);
        rni[r] = inv_tau / fmaxf(sqrtf(s), 1e-12f);
    }

    // --- initial mean: per-warp partials, conflict-free scalar stores ---
    {
        float pm[8];
        #pragma unroll
        for (int j = 0; j < 8; j++)
            pm[j] = hv[0][j] + hv[1][j] + hv[2][j] + hv[3][j];
        #pragma unroll
        for (int j = 0; j < 8; j++)
            pmu[w][32 * j + l] = pm[j];
    }
    __syncthreads();
    if (t < DD) {
        float acc = 0.0f;
        #pragma unroll
        for (int ww = 0; ww < 16; ww++) acc += pmu[ww][t];
        mu_s[t] = acc * (1.0f / NN);
    }
    __syncthreads();

    // --- 3 EM iterations, 3 barriers each ---
    for (int it = 0; it < NIT; it++) {
        // load mu slice + redundant ||mu|| per warp
        float mn[8];
        float nq = 0.0f;
        #pragma unroll
        for (int j = 0; j < 8; j++) {
            mn[j] = mu_s[32 * j + l];
            nq += mn[j] * mn[j];
        }
        nq = wsum(nq);
        const float inv_nm = 1.0f / fmaxf(sqrtf(nq), 1e-12f);

        // sim for this warp's 4 rows (raw dot * rni; mu-norm applied later)
        #pragma unroll
        for (int r = 0; r < 4; r++) {
            float d = 0.0f;
            #pragma unroll
            for (int j = 0; j < 8; j++) d += hv[r][j] * mn[j];
            d = wsum(d);
            if (l == 0) simv[4 * w + r] = d * rni[r];
        }
        __syncthreads();   // (1) simv ready

        // redundant softmax in every warp
        float s0 = simv[l] * inv_nm;
        float s1 = simv[l + 32] * inv_nm;
        float mx = fmaxf(s0, s1);
        #pragma unroll
        for (int o = 16; o > 0; o >>= 1)
            mx = fmaxf(mx, __shfl_xor_sync(0xFFFFFFFFu, mx, o));
        float e0 = expf(s0 - mx);
        float e1 = expf(s1 - mx);
        float inv = 1.0f / wsum(e0 + e1);
        float a_lo = e0 * inv;
        float a_hi = e1 * inv;

        if (it == NIT - 1 && w == 0) {
            out_alpha[(size_t)b * NN + l]      = a_lo;
            out_alpha[(size_t)b * NN + l + 32] = a_hi;
        }

        // pull this warp's 4 alphas via shuffle
        float al[4];
        #pragma unroll
        for (int r = 0; r < 4; r++) {
            int n = 4 * w + r;
            al[r] = (n < 32) ? __shfl_sync(0xFFFFFFFFu, a_lo, n)
                             : __shfl_sync(0xFFFFFFFFu, a_hi, n - 32);
        }

        // mu update partials (conflict-free scalar stores)
        float pm[8];
        #pragma unroll
        for (int j = 0; j < 8; j++)
            pm[j] = al[0] * hv[0][j] + al[1] * hv[1][j]
                  + al[2] * hv[2][j] + al[3] * hv[3][j];
        #pragma unroll
        for (int j = 0; j < 8; j++)
            pmu[w][32 * j + l] = pm[j];
        __syncthreads();   // (2) pmu ready

        if (t < DD) {
            float acc = 0.0f;
            #pragma unroll
            for (int ww = 0; ww < 16; ww++) acc += pmu[ww][t];
            if (it == NIT - 1) out_mu[(size_t)b * DD + t] = acc;
            else               mu_s[t] = acc;
        }
        if (it < NIT - 1) __syncthreads();   // (3) mu_s ready
    }
}

// ---------------------------------------------------------------------------
// Kernel 2: fused MLP. 128 threads, 16 rows/block.
// Thread tile: 8 consecutive cols x 8 rows, packed f32x2 FFMA.
// ---------------------------------------------------------------------------
__global__ void __launch_bounds__(128, 4)
mlp_kernel(const float* __restrict__ mu_in,   // [B, 256]
           const float* __restrict__ b1,
           const float* __restrict__ g1,
           const float* __restrict__ be1,
           const float* __restrict__ b2,
           const float* __restrict__ g2,
           const float* __restrict__ be2,
           float* __restrict__ theta)         // [B, 512]
{
    __shared__ float xs[16 * OUTD];           // 32KB

    const int t = threadIdx.x;                 // 0..127
    const int row0 = blockIdx.x * 16;
    const int ox8 = (t & 63) * 8;              // 8 consecutive output cols
    const int ry = (t >> 6) * 8;               // row base {0, 8}
    const int w = t >> 5;                      // warp 0..3
    const int l = t & 31;

    // --- load mu tile [16,256] (1024 float4 / 128 thr = 8 each) ---
    {
        const float4* src = (const float4*)(mu_in + (size_t)row0 * DD);
        float4* dst = (float4*)xs;
        #pragma unroll
        for (int i = 0; i < 8; i++)
            dst[t + 128 * i] = src[t + 128 * i];
    }
    __syncthreads();

    unsigned long long a0[8], a1[8], a2[8], a3[8];
    #pragma unroll
    for (int r = 0; r < 8; r++) { a0[r]=0ull; a1[r]=0ull; a2[r]=0ull; a3[r]=0ull; }

    // --- GEMM1: y1 = mu @ w1^T ---
    for (int k = 0; k < DD; k += 2) {
        float2 m[8];
        #pragma unroll
        for (int r = 0; r < 8; r++)
            m[r] = *(const float2*)(xs + (ry + r) * DD + k);
        #pragma unroll
        for (int kk = 0; kk < 2; kk++) {
            ulonglong2 wlo = *(const ulonglong2*)(g_w1t + (size_t)(k + kk) * OUTD + ox8);
            ulonglong2 whi = *(const ulonglong2*)(g_w1t + (size_t)(k + kk) * OUTD + ox8 + 4);
            #pragma unroll
            for (int r = 0; r < 8; r++) {
                unsigned long long d;
                DUP2(d, __float_as_uint(kk ? m[r].y : m[r].x));
                FMA2(a0[r], wlo.x, d);
                FMA2(a1[r], wlo.y, d);
                FMA2(a2[r], whi.x, d);
                FMA2(a3[r], whi.y, d);
            }
        }
    }
    __syncthreads();

    // --- y1 + b1 into xs[16][512] ---
    {
        const float4 bb0 = *(const float4*)(b1 + ox8);
        const float4 bb1 = *(const float4*)(b1 + ox8 + 4);
        #pragma unroll
        for (int r = 0; r < 8; r++) {
            unsigned u0,u1,u2,u3,u4,u5,u6,u7;
            UNPK2(u0,u1,a0[r]); UNPK2(u2,u3,a1[r]);
            UNPK2(u4,u5,a2[r]); UNPK2(u6,u7,a3[r]);
            *(float4*)(xs + (ry + r) * OUTD + ox8) =
                make_float4(__uint_as_float(u0)+bb0.x, __uint_as_float(u1)+bb0.y,
                            __uint_as_float(u2)+bb0.z, __uint_as_float(u3)+bb0.w);
            *(float4*)(xs + (ry + r) * OUTD + ox8 + 4) =
                make_float4(__uint_as_float(u4)+bb1.x, __uint_as_float(u5)+bb1.y,
                            __uint_as_float(u6)+bb1.z, __uint_as_float(u7)+bb1.w);
        }
    }
    __syncthreads();

    // --- LN1 + exact GELU (warp w handles rows 4w..4w+3) ---
    #pragma unroll
    for (int rr = 0; rr < 4; rr++) {
        const int row = w * 4 + rr;
        float s = 0.0f, sq = 0.0f;
        #pragma unroll
        for (int j = 0; j < 16; j++) {
            float v = xs[row * OUTD + l + 32 * j];
            s += v; sq += v * v;
        }
        #pragma unroll
        for (int o = 16; o > 0; o >>= 1) {
            s  += __shfl_xor_sync(0xFFFFFFFFu, s, o);
            sq += __shfl_xor_sync(0xFFFFFFFFu, sq, o);
        }
        const float mean = s * (1.0f / OUTD);
        const float var  = sq * (1.0f / OUTD) - mean * mean;
        const float rstd = rsqrtf(var + 1e-5f);
        #pragma unroll
        for (int j = 0; j < 16; j++) {
            const int idx = l + 32 * j;
            float v = xs[row * OUTD + idx];
            v = (v - mean) * rstd * g1[idx] + be1[idx];
            v = 0.5f * v * (1.0f + erff(v * 0.70710678118654752f));
            xs[row * OUTD + idx] = v;
        }
    }
    __syncthreads();

    // --- GEMM2: y2 = x @ w2^T ---
    #pragma unroll
    for (int r = 0; r < 8; r++) { a0[r]=0ull; a1[r]=0ull; a2[r]=0ull; a3[r]=0ull; }

    for (int k = 0; k < OUTD; k += 2) {
        float2 m[8];
        #pragma unroll
        for (int r = 0; r < 8; r++)
            m[r] = *(const float2*)(xs + (ry + r) * OUTD + k);
        #pragma unroll
        for (int kk = 0; kk < 2; kk++) {
            ulonglong2 wlo = *(const ulonglong2*)(g_w2t + (size_t)(k + kk) * OUTD + ox8);
            ulonglong2 whi = *(const ulonglong2*)(g_w2t + (size_t)(k + kk) * OUTD + ox8 + 4);
            #pragma unroll
            for (int r = 0; r < 8; r++) {
                unsigned long long d;
                DUP2(d, __float_as_uint(kk ? m[r].y : m[r].x));
                FMA2(a0[r], wlo.x, d);
                FMA2(a1[r], wlo.y, d);
                FMA2(a2[r], whi.x, d);
                FMA2(a3[r], whi.y, d);
            }
        }
    }
    __syncthreads();

    // --- y2 + b2 ---
    {
        const float4 bb0 = *(const float4*)(b2 + ox8);
        const float4 bb1 = *(const float4*)(b2 + ox8 + 4);
        #pragma unroll
        for (int r = 0; r < 8; r++) {
            unsigned u0,u1,u2,u3,u4,u5,u6,u7;
            UNPK2(u0,u1,a0[r]); UNPK2(u2,u3,a1[r]);
            UNPK2(u4,u5,a2[r]); UNPK2(u6,u7,a3[r]);
            *(float4*)(xs + (ry + r) * OUTD + ox8) =
                make_float4(__uint_as_float(u0)+bb0.x, __uint_as_float(u1)+bb0.y,
                            __uint_as_float(u2)+bb0.z, __uint_as_float(u3)+bb0.w);
            *(float4*)(xs + (ry + r) * OUTD + ox8 + 4) =
                make_float4(__uint_as_float(u4)+bb1.x, __uint_as_float(u5)+bb1.y,
                            __uint_as_float(u6)+bb1.z, __uint_as_float(u7)+bb1.w);
        }
    }
    __syncthreads();

    // --- LN2 ---
    #pragma unroll
    for (int rr = 0; rr < 4; rr++) {
        const int row = w * 4 + rr;
        float s = 0.0f, sq = 0.0f;
        #pragma unroll
        for (int j = 0; j < 16; j++) {
            float v = xs[row * OUTD + l + 32 * j];
            s += v; sq += v * v;
        }
        #pragma unroll
        for (int o = 16; o > 0; o >>= 1) {
            s  += __shfl_xor_sync(0xFFFFFFFFu, s, o);
            sq += __shfl_xor_sync(0xFFFFFFFFu, sq, o);
        }
        const float mean = s * (1.0f / OUTD);
        const float var  = sq * (1.0f / OUTD) - mean * mean;
        const float rstd = rsqrtf(var + 1e-5f);
        #pragma unroll
        for (int j = 0; j < 16; j++) {
            const int idx = l + 32 * j;
            float v = xs[row * OUTD + idx];
            xs[row * OUTD + idx] = (v - mean) * rstd * g2[idx] + be2[idx];
        }
    }
    __syncthreads();

    // --- write theta tile (2048 float4 / 128 thr = 16 each) ---
    {
        float4* dst = (float4*)(theta + (size_t)row0 * OUTD);
        const float4* src = (const float4*)xs;
        #pragma unroll
        for (int i = 0; i < 16; i++)
            dst[t + 128 * i] = src[t + 128 * i];
    }
}

// ---------------------------------------------------------------------------
// Launch. Output layout: [theta (B*512) | alpha (B*64) | mu (B*256)]
// ---------------------------------------------------------------------------
extern "C" void kernel_launch(void* const* d_in, const int* in_sizes, int n_in,
                              void* d_out, int out_size)
{
    const float* h       = (const float*)d_in[0];
    const float* log_tau = (const float*)d_in[1];
    const float* w1      = (const float*)d_in[2];
    const float* b1      = (const float*)d_in[3];
    const float* g1      = (const float*)d_in[4];
    const float* be1     = (const float*)d_in[5];
    const float* w2      = (const float*)d_in[6];
    const float* b2      = (const float*)d_in[7];
    const float* g2      = (const float*)d_in[8];
    const float* be2     = (const float*)d_in[9];

    const int batch = in_sizes[0] / (NN * DD);

    float* out   = (float*)d_out;
    float* theta = out;
    float* alpha = out + (size_t)batch * OUTD;
    float* mu    = out + (size_t)batch * OUTD + (size_t)batch * NN;

    float* w1t_dev = nullptr;
    float* w2t_dev = nullptr;
    cudaGetSymbolAddress((void**)&w1t_dev, g_w1t);
    cudaGetSymbolAddress((void**)&w2t_dev, g_w2t);

    dim3 tb(32, 8);
    transpose_kernel<<<dim3(DD / 32, OUTD / 32), tb>>>(w1, w1t_dev, OUTD, DD);
    transpose_kernel<<<dim3(OUTD / 32, OUTD / 32), tb>>>(w2, w2t_dev, OUTD, OUTD);

    cluster_kernel<<<batch, 512>>>(h, log_tau, alpha, mu);
    mlp_kernel<<<batch / 16, 128>>>(mu, b1, g1, be1, b2, g2, be2, theta);
}

// round 5
// speedup vs baseline: 1.4738x; 1.4738x over previous
#include <cuda_runtime.h>
#include <math.h>

#define BB   4096
#define NN   64
#define DD   256
#define OUTD 512
#define NIT  3

// Transposed weight scratch
__device__ float g_w1t[DD * OUTD];    // [256][512]
__device__ float g_w2t[OUTD * OUTD];  // [512][512]

// ---- packed f32x2 helpers (sm_100+) ----
#define FMA2(d, a, b) asm("fma.rn.f32x2 %0, %1, %2, %0;" : "+l"(d) : "l"(a), "l"(b))
#define DUP2(d, s)    asm("mov.b64 %0, {%1, %1};" : "=l"(d) : "r"(s))
#define UNPK2(lo, hi, d) asm("mov.b64 {%0, %1}, %2;" : "=r"(lo), "=r"(hi) : "l"(d))

// ---------------------------------------------------------------------------
// Tiled transpose: out[c][r] = in[r][c], in is [R][C]
// ---------------------------------------------------------------------------
__global__ void transpose_kernel(const float* __restrict__ in,
                                 float* __restrict__ out, int R, int C)
{
    __shared__ float tile[32][33];
    const int c0 = blockIdx.x * 32;
    const int r0 = blockIdx.y * 32;
    const int tx = threadIdx.x;
    const int ty = threadIdx.y;
    #pragma unroll
    for (int i = 0; i < 4; i++) {
        int r = r0 + ty + 8 * i;
        int c = c0 + tx;
        if (r < R && c < C) tile[ty + 8 * i][tx] = in[(size_t)r * C + c];
    }
    __syncthreads();
    #pragma unroll
    for (int i = 0; i < 4; i++) {
        int c = c0 + ty + 8 * i;
        int r = r0 + tx;
        if (r < R && c < C) out[(size_t)c * R + r] = tile[tx][ty + 8 * i];
    }
}

__device__ __forceinline__ float wsum(float v) {
    #pragma unroll
    for (int o = 16; o > 0; o >>= 1) v += __shfl_xor_sync(0xFFFFFFFFu, v, o);
    return v;
}

// ---------------------------------------------------------------------------
// Kernel 1: soft clustering. 512 threads/block, one batch per block.
// Warp w (0..15) owns rows 4w..4w+3.
// Lane l owns dims {4l..4l+3} and {128+4l..128+4l+3}: all float4 smem
// accesses have 16B lane stride -> conflict-free; gmem stays coalesced.
// ---------------------------------------------------------------------------
__global__ void __launch_bounds__(512, 2)
cluster_kernel(const float* __restrict__ h,
               const float* __restrict__ log_tau,
               float* __restrict__ out_alpha,   // [B, 64]
               float* __restrict__ out_mu)      // [B, 256]
{
    __shared__ float pmu[16][DD];    // per-warp partial mu (16KB)
    __shared__ float mun_s[DD];
    __shared__ float simv[NN];
    __shared__ float alpha_s[NN];
    __shared__ float red[8];

    const int b = blockIdx.x;
    const int t = threadIdx.x;       // 0..511
    const int w = t >> 5;            // 0..15
    const int l = t & 31;

    const float* hb = h + (size_t)b * NN * DD;

    // --- load 4 rows x (2 x float4) into registers ---
    float4 hv[4][2];
    #pragma unroll
    for (int r = 0; r < 4; r++) {
        const float* p = hb + (size_t)(4 * w + r) * DD + 4 * l;
        hv[r][0] = *(const float4*)(p);
        hv[r][1] = *(const float4*)(p + 128);
    }

    float tau = expf(log_tau[0]);
    tau = fminf(fmaxf(tau, 0.01f), 2.0f);
    const float inv_tau = 1.0f / tau;

    // --- per-row inverse norms, pre-multiplied by 1/tau ---
    float rni[4];
    #pragma unroll
    for (int r = 0; r < 4; r++) {
        float4 a = hv[r][0], c = hv[r][1];
        float s = a.x*a.x + a.y*a.y + a.z*a.z + a.w*a.w
                + c.x*c.x + c.y*c.y + c.z*c.z + c.w*c.w;
        s = wsum(s);
        rni[r] = inv_tau / fmaxf(sqrtf(s), 1e-12f);
    }

    // --- per-warp partial sums for initial mean (conflict-free stores) ---
    float pm[8];
    #pragma unroll
    for (int i = 0; i < 8; i++) pm[i] = 0.0f;
    #pragma unroll
    for (int r = 0; r < 4; r++) {
        pm[0] += hv[r][0].x; pm[1] += hv[r][0].y;
        pm[2] += hv[r][0].z; pm[3] += hv[r][0].w;
        pm[4] += hv[r][1].x; pm[5] += hv[r][1].y;
        pm[6] += hv[r][1].z; pm[7] += hv[r][1].w;
    }
    *(float4*)&pmu[w][4 * l]       = make_float4(pm[0], pm[1], pm[2], pm[3]);
    *(float4*)&pmu[w][128 + 4 * l] = make_float4(pm[4], pm[5], pm[6], pm[7]);
    __syncthreads();

    // threads 0..255 own one mu dim each (scalar, conflict-free)
    float mval = 0.0f;
    if (t < DD) {
        #pragma unroll
        for (int ww = 0; ww < 16; ww++) mval += pmu[ww][t];
        mval *= (1.0f / NN);
    }

    // --- 3 EM iterations ---
    for (int it = 0; it < NIT; it++) {
        // ||mu||: reduce mval^2 over dims (warps 0..7)
        if (t < DD) {
            float s = wsum(mval * mval);
            if (l == 0) red[w] = s;
        }
        __syncthreads();
        if (t < DD) {
            float tot = red[0] + red[1] + red[2] + red[3]
                      + red[4] + red[5] + red[6] + red[7];
            mun_s[t] = mval / fmaxf(sqrtf(tot), 1e-12f);
        }
        __syncthreads();

        // sim for this warp's 4 rows (conflict-free float4 loads)
        float4 mn0 = *(const float4*)(mun_s + 4 * l);
        float4 mn1 = *(const float4*)(mun_s + 128 + 4 * l);
        #pragma unroll
        for (int r = 0; r < 4; r++) {
            float4 a = hv[r][0], c = hv[r][1];
            float d = a.x*mn0.x + a.y*mn0.y + a.z*mn0.z + a.w*mn0.w
                    + c.x*mn1.x + c.y*mn1.y + c.z*mn1.z + c.w*mn1.w;
            d = wsum(d);
            if (l == 0) simv[4 * w + r] = d * rni[r];
        }
        __syncthreads();

        // softmax over 64 (warp 0)
        if (w == 0) {
            float a = simv[l];
            float c = simv[l + 32];
            float mx = fmaxf(a, c);
            #pragma unroll
            for (int o = 16; o > 0; o >>= 1)
                mx = fmaxf(mx, __shfl_xor_sync(0xFFFFFFFFu, mx, o));
            float e0 = expf(a - mx);
            float e1 = expf(c - mx);
            float ss = wsum(e0 + e1);
            float inv = 1.0f / ss;
            alpha_s[l]      = e0 * inv;
            alpha_s[l + 32] = e1 * inv;
        }
        __syncthreads();

        // mu update: per-warp partials (conflict-free float4 stores)
        float al[4];
        #pragma unroll
        for (int r = 0; r < 4; r++) al[r] = alpha_s[4 * w + r];
        #pragma unroll
        for (int i = 0; i < 8; i++) pm[i] = 0.0f;
        #pragma unroll
        for (int r = 0; r < 4; r++) {
            const float a = al[r];
            pm[0] += a * hv[r][0].x; pm[1] += a * hv[r][0].y;
            pm[2] += a * hv[r][0].z; pm[3] += a * hv[r][0].w;
            pm[4] += a * hv[r][1].x; pm[5] += a * hv[r][1].y;
            pm[6] += a * hv[r][1].z; pm[7] += a * hv[r][1].w;
        }
        *(float4*)&pmu[w][4 * l]       = make_float4(pm[0], pm[1], pm[2], pm[3]);
        *(float4*)&pmu[w][128 + 4 * l] = make_float4(pm[4], pm[5], pm[6], pm[7]);
        __syncthreads();
        if (t < DD) {
            float acc = 0.0f;
            #pragma unroll
            for (int ww = 0; ww < 16; ww++) acc += pmu[ww][t];
            mval = acc;
        }
        __syncthreads();
    }

    // --- outputs ---
    if (t < NN) out_alpha[(size_t)b * NN + t] = alpha_s[t];
    if (t < DD) out_mu[(size_t)b * DD + t] = mval;
}

// ---------------------------------------------------------------------------
// Kernel 2: fused MLP. 256 threads, 16 rows/block.
// Thread tile: 4 consecutive cols x 8 rows, packed f32x2 FFMA.
// ---------------------------------------------------------------------------
__global__ void __launch_bounds__(256, 3)
mlp_kernel(const float* __restrict__ mu_in,   // [B, 256]
           const float* __restrict__ b1,
           const float* __restrict__ g1,
           const float* __restrict__ be1,
           const float* __restrict__ b2,
           const float* __restrict__ g2,
           const float* __restrict__ be2,
           float* __restrict__ theta)         // [B, 512]
{
    __shared__ float xs[16 * OUTD];           // 32KB

    const int t = threadIdx.x;                 // 0..255
    const int row0 = blockIdx.x * 16;
    const int ox4 = (t & 127) * 4;             // 4 consecutive output cols
    const int ry = (t >> 7) * 8;               // row base {0, 8}
    const int w = t >> 5;                      // warp 0..7
    const int l = t & 31;

    // --- load mu tile [16,256] (1024 float4 / 256 thr = 4 each) ---
    {
        const float4* src = (const float4*)(mu_in + (size_t)row0 * DD);
        float4* dst = (float4*)xs;
        #pragma unroll
        for (int i = 0; i < 4; i++)
            dst[t + 256 * i] = src[t + 256 * i];
    }
    __syncthreads();

    unsigned long long a01[8], a23[8];
    #pragma unroll
    for (int r = 0; r < 8; r++) { a01[r] = 0ull; a23[r] = 0ull; }

    // --- GEMM1: y1 = mu @ w1^T ---
    for (int k = 0; k < DD; k += 4) {
        float4 m[8];
        #pragma unroll
        for (int r = 0; r < 8; r++)
            m[r] = *(const float4*)(xs + (ry + r) * DD + k);  // broadcast
        #pragma unroll
        for (int kk = 0; kk < 4; kk++) {
            ulonglong2 wp = *(const ulonglong2*)(g_w1t + (size_t)(k + kk) * OUTD + ox4);
            #pragma unroll
            for (int r = 0; r < 8; r++) {
                float mv = (kk == 0) ? m[r].x : (kk == 1) ? m[r].y
                         : (kk == 2) ? m[r].z : m[r].w;
                unsigned long long d;
                DUP2(d, __float_as_uint(mv));
                FMA2(a01[r], wp.x, d);
                FMA2(a23[r], wp.y, d);
            }
        }
    }
    __syncthreads();

    // --- y1 + b1 into xs[16][512] ---
    {
        const float4 bb = *(const float4*)(b1 + ox4);
        #pragma unroll
        for (int r = 0; r < 8; r++) {
            unsigned u0, u1, u2, u3;
            UNPK2(u0, u1, a01[r]);
            UNPK2(u2, u3, a23[r]);
            *(float4*)(xs + (ry + r) * OUTD + ox4) =
                make_float4(__uint_as_float(u0) + bb.x, __uint_as_float(u1) + bb.y,
                            __uint_as_float(u2) + bb.z, __uint_as_float(u3) + bb.w);
        }
    }
    __syncthreads();

    // --- LN1 + exact GELU (warp w handles rows 2w, 2w+1) ---
    #pragma unroll
    for (int rr = 0; rr < 2; rr++) {
        const int row = w * 2 + rr;
        float s = 0.0f, sq = 0.0f;
        #pragma unroll
        for (int j = 0; j < 16; j++) {
            float v = xs[row * OUTD + l + 32 * j];
            s += v; sq += v * v;
        }
        #pragma unroll
        for (int o = 16; o > 0; o >>= 1) {
            s  += __shfl_xor_sync(0xFFFFFFFFu, s, o);
            sq += __shfl_xor_sync(0xFFFFFFFFu, sq, o);
        }
        const float mean = s * (1.0f / OUTD);
        const float var  = sq * (1.0f / OUTD) - mean * mean;
        const float rstd = rsqrtf(var + 1e-5f);
        #pragma unroll
        for (int j = 0; j < 16; j++) {
            const int idx = l + 32 * j;
            float v = xs[row * OUTD + idx];
            v = (v - mean) * rstd * g1[idx] + be1[idx];
            v = 0.5f * v * (1.0f + erff(v * 0.70710678118654752f));
            xs[row * OUTD + idx] = v;
        }
    }
    __syncthreads();

    // --- GEMM2: y2 = x @ w2^T ---
    #pragma unroll
    for (int r = 0; r < 8; r++) { a01[r] = 0ull; a23[r] = 0ull; }

    for (int k = 0; k < OUTD; k += 4) {
        float4 m[8];
        #pragma unroll
        for (int r = 0; r < 8; r++)
            m[r] = *(const float4*)(xs + (ry + r) * OUTD + k);
        #pragma unroll
        for (int kk = 0; kk < 4; kk++) {
            ulonglong2 wp = *(const ulonglong2*)(g_w2t + (size_t)(k + kk) * OUTD + ox4);
            #pragma unroll
            for (int r = 0; r < 8; r++) {
                float mv = (kk == 0) ? m[r].x : (kk == 1) ? m[r].y
                         : (kk == 2) ? m[r].z : m[r].w;
                unsigned long long d;
                DUP2(d, __float_as_uint(mv));
                FMA2(a01[r], wp.x, d);
                FMA2(a23[r], wp.y, d);
            }
        }
    }
    __syncthreads();

    // --- y2 + b2 ---
    {
        const float4 bb = *(const float4*)(b2 + ox4);
        #pragma unroll
        for (int r = 0; r < 8; r++) {
            unsigned u0, u1, u2, u3;
            UNPK2(u0, u1, a01[r]);
            UNPK2(u2, u3, a23[r]);
            *(float4*)(xs + (ry + r) * OUTD + ox4) =
                make_float4(__uint_as_float(u0) + bb.x, __uint_as_float(u1) + bb.y,
                            __uint_as_float(u2) + bb.z, __uint_as_float(u3) + bb.w);
        }
    }
    __syncthreads();

    // --- LN2 ---
    #pragma unroll
    for (int rr = 0; rr < 2; rr++) {
        const int row = w * 2 + rr;
        float s = 0.0f, sq = 0.0f;
        #pragma unroll
        for (int j = 0; j < 16; j++) {
            float v = xs[row * OUTD + l + 32 * j];
            s += v; sq += v * v;
        }
        #pragma unroll
        for (int o = 16; o > 0; o >>= 1) {
            s  += __shfl_xor_sync(0xFFFFFFFFu, s, o);
            sq += __shfl_xor_sync(0xFFFFFFFFu, sq, o);
        }
        const float mean = s * (1.0f / OUTD);
        const float var  = sq * (1.0f / OUTD) - mean * mean;
        const float rstd = rsqrtf(var + 1e-5f);
        #pragma unroll
        for (int j = 0; j < 16; j++) {
            const int idx = l + 32 * j;
            float v = xs[row * OUTD + idx];
            xs[row * OUTD + idx] = (v - mean) * rstd * g2[idx] + be2[idx];
        }
    }
    __syncthreads();

    // --- write theta tile (2048 float4 / 256 thr = 8 each) ---
    {
        float4* dst = (float4*)(theta + (size_t)row0 * OUTD);
        const float4* src = (const float4*)xs;
        #pragma unroll
        for (int i = 0; i < 8; i++)
            dst[t + 256 * i] = src[t + 256 * i];
    }
}

// ---------------------------------------------------------------------------
// Launch. Output layout: [theta (B*512) | alpha (B*64) | mu (B*256)]
// ---------------------------------------------------------------------------
extern "C" void kernel_launch(void* const* d_in, const int* in_sizes, int n_in,
                              void* d_out, int out_size)
{
    const float* h       = (const float*)d_in[0];
    const float* log_tau = (const float*)d_in[1];
    const float* w1      = (const float*)d_in[2];
    const float* b1      = (const float*)d_in[3];
    const float* g1      = (const float*)d_in[4];
    const float* be1     = (const float*)d_in[5];
    const float* w2      = (const float*)d_in[6];
    const float* b2      = (const float*)d_in[7];
    const float* g2      = (const float*)d_in[8];
    const float* be2     = (const float*)d_in[9];

    const int batch = in_sizes[0] / (NN * DD);

    float* out   = (float*)d_out;
    float* theta = out;
    float* alpha = out + (size_t)batch * OUTD;
    float* mu    = out + (size_t)batch * OUTD + (size_t)batch * NN;

    float* w1t_dev = nullptr;
    float* w2t_dev = nullptr;
    cudaGetSymbolAddress((void**)&w1t_dev, g_w1t);
    cudaGetSymbolAddress((void**)&w2t_dev, g_w2t);

    dim3 tb(32, 8);
    transpose_kernel<<<dim3(DD / 32, OUTD / 32), tb>>>(w1, w1t_dev, OUTD, DD);
    transpose_kernel<<<dim3(OUTD / 32, OUTD / 32), tb>>>(w2, w2t_dev, OUTD, OUTD);

    cluster_kernel<<<batch, 512>>>(h, log_tau, alpha, mu);
    mlp_kernel<<<batch / 16, 256>>>(mu, b1, g1, be1, b2, g2, be2, theta);
}

// round 6
// speedup vs baseline: 2.0399x; 1.3841x over previous
#include <cuda_runtime.h>
#include <math.h>

#define BB   4096
#define NN   64
#define DD   256
#define OUTD 512
#define NIT  3

// Transposed weight scratch
__device__ float g_w1t[DD * OUTD];    // [256][512]
__device__ float g_w2t[OUTD * OUTD];  // [512][512]

// ---- packed f32x2 helpers (sm_100+) ----
#define FMA2(d, a, b) asm("fma.rn.f32x2 %0, %1, %2, %0;" : "+l"(d) : "l"(a), "l"(b))
#define DUP2(d, s)    asm("mov.b64 %0, {%1, %1};" : "=l"(d) : "r"(s))
#define UNPK2(lo, hi, d) asm("mov.b64 {%0, %1}, %2;" : "=r"(lo), "=r"(hi) : "l"(d))

// ---------------------------------------------------------------------------
// Tiled transpose: out[c][r] = in[r][c], in is [R][C]
// ---------------------------------------------------------------------------
__global__ void transpose_kernel(const float* __restrict__ in,
                                 float* __restrict__ out, int R, int C)
{
    __shared__ float tile[32][33];
    const int c0 = blockIdx.x * 32;
    const int r0 = blockIdx.y * 32;
    const int tx = threadIdx.x;
    const int ty = threadIdx.y;
    #pragma unroll
    for (int i = 0; i < 4; i++) {
        int r = r0 + ty + 8 * i;
        int c = c0 + tx;
        if (r < R && c < C) tile[ty + 8 * i][tx] = in[(size_t)r * C + c];
    }
    __syncthreads();
    #pragma unroll
    for (int i = 0; i < 4; i++) {
        int c = c0 + ty + 8 * i;
        int r = r0 + tx;
        if (r < R && c < C) out[(size_t)c * R + r] = tile[tx][ty + 8 * i];
    }
}

__device__ __forceinline__ float wsum(float v) {
    #pragma unroll
    for (int o = 16; o > 0; o >>= 1) v += __shfl_xor_sync(0xFFFFFFFFu, v, o);
    return v;
}

// ---------------------------------------------------------------------------
// Kernel 1: soft clustering. 512 threads/block, one batch per block.
// (unchanged from round 5 — conflict-free smem, known-good ~99us)
// ---------------------------------------------------------------------------
__global__ void __launch_bounds__(512, 2)
cluster_kernel(const float* __restrict__ h,
               const float* __restrict__ log_tau,
               float* __restrict__ out_alpha,   // [B, 64]
               float* __restrict__ out_mu)      // [B, 256]
{
    __shared__ float pmu[16][DD];    // per-warp partial mu (16KB)
    __shared__ float mun_s[DD];
    __shared__ float simv[NN];
    __shared__ float alpha_s[NN];
    __shared__ float red[8];

    const int b = blockIdx.x;
    const int t = threadIdx.x;       // 0..511
    const int w = t >> 5;            // 0..15
    const int l = t & 31;

    const float* hb = h + (size_t)b * NN * DD;

    // --- load 4 rows x (2 x float4) into registers ---
    float4 hv[4][2];
    #pragma unroll
    for (int r = 0; r < 4; r++) {
        const float* p = hb + (size_t)(4 * w + r) * DD + 4 * l;
        hv[r][0] = *(const float4*)(p);
        hv[r][1] = *(const float4*)(p + 128);
    }

    float tau = expf(log_tau[0]);
    tau = fminf(fmaxf(tau, 0.01f), 2.0f);
    const float inv_tau = 1.0f / tau;

    // --- per-row inverse norms, pre-multiplied by 1/tau ---
    float rni[4];
    #pragma unroll
    for (int r = 0; r < 4; r++) {
        float4 a = hv[r][0], c = hv[r][1];
        float s = a.x*a.x + a.y*a.y + a.z*a.z + a.w*a.w
                + c.x*c.x + c.y*c.y + c.z*c.z + c.w*c.w;
        s = wsum(s);
        rni[r] = inv_tau / fmaxf(sqrtf(s), 1e-12f);
    }

    // --- per-warp partial sums for initial mean ---
    float pm[8];
    #pragma unroll
    for (int i = 0; i < 8; i++) pm[i] = 0.0f;
    #pragma unroll
    for (int r = 0; r < 4; r++) {
        pm[0] += hv[r][0].x; pm[1] += hv[r][0].y;
        pm[2] += hv[r][0].z; pm[3] += hv[r][0].w;
        pm[4] += hv[r][1].x; pm[5] += hv[r][1].y;
        pm[6] += hv[r][1].z; pm[7] += hv[r][1].w;
    }
    *(float4*)&pmu[w][4 * l]       = make_float4(pm[0], pm[1], pm[2], pm[3]);
    *(float4*)&pmu[w][128 + 4 * l] = make_float4(pm[4], pm[5], pm[6], pm[7]);
    __syncthreads();

    float mval = 0.0f;
    if (t < DD) {
        #pragma unroll
        for (int ww = 0; ww < 16; ww++) mval += pmu[ww][t];
        mval *= (1.0f / NN);
    }

    // --- 3 EM iterations ---
    for (int it = 0; it < NIT; it++) {
        if (t < DD) {
            float s = wsum(mval * mval);
            if (l == 0) red[w] = s;
        }
        __syncthreads();
        if (t < DD) {
            float tot = red[0] + red[1] + red[2] + red[3]
                      + red[4] + red[5] + red[6] + red[7];
            mun_s[t] = mval / fmaxf(sqrtf(tot), 1e-12f);
        }
        __syncthreads();

        float4 mn0 = *(const float4*)(mun_s + 4 * l);
        float4 mn1 = *(const float4*)(mun_s + 128 + 4 * l);
        #pragma unroll
        for (int r = 0; r < 4; r++) {
            float4 a = hv[r][0], c = hv[r][1];
            float d = a.x*mn0.x + a.y*mn0.y + a.z*mn0.z + a.w*mn0.w
                    + c.x*mn1.x + c.y*mn1.y + c.z*mn1.z + c.w*mn1.w;
            d = wsum(d);
            if (l == 0) simv[4 * w + r] = d * rni[r];
        }
        __syncthreads();

        if (w == 0) {
            float a = simv[l];
            float c = simv[l + 32];
            float mx = fmaxf(a, c);
            #pragma unroll
            for (int o = 16; o > 0; o >>= 1)
                mx = fmaxf(mx, __shfl_xor_sync(0xFFFFFFFFu, mx, o));
            float e0 = expf(a - mx);
            float e1 = expf(c - mx);
            float ss = wsum(e0 + e1);
            float inv = 1.0f / ss;
            alpha_s[l]      = e0 * inv;
            alpha_s[l + 32] = e1 * inv;
        }
        __syncthreads();

        float al[4];
        #pragma unroll
        for (int r = 0; r < 4; r++) al[r] = alpha_s[4 * w + r];
        #pragma unroll
        for (int i = 0; i < 8; i++) pm[i] = 0.0f;
        #pragma unroll
        for (int r = 0; r < 4; r++) {
            const float a = al[r];
            pm[0] += a * hv[r][0].x; pm[1] += a * hv[r][0].y;
            pm[2] += a * hv[r][0].z; pm[3] += a * hv[r][0].w;
            pm[4] += a * hv[r][1].x; pm[5] += a * hv[r][1].y;
            pm[6] += a * hv[r][1].z; pm[7] += a * hv[r][1].w;
        }
        *(float4*)&pmu[w][4 * l]       = make_float4(pm[0], pm[1], pm[2], pm[3]);
        *(float4*)&pmu[w][128 + 4 * l] = make_float4(pm[4], pm[5], pm[6], pm[7]);
        __syncthreads();
        if (t < DD) {
            float acc = 0.0f;
            #pragma unroll
            for (int ww = 0; ww < 16; ww++) acc += pmu[ww][t];
            mval = acc;
        }
        __syncthreads();
    }

    if (t < NN) out_alpha[(size_t)b * NN + t] = alpha_s[t];
    if (t < DD) out_mu[(size_t)b * DD + t] = mval;
}

// ---------------------------------------------------------------------------
// Kernel 2: fused MLP. 256 threads, 8 rows/block -> grid = B/8 = 512 blocks.
// Thread tile: 4 consecutive cols x 4 rows (round-3 proven microkernel).
// ---------------------------------------------------------------------------
__global__ void __launch_bounds__(256, 4)
mlp_kernel(const float* __restrict__ mu_in,   // [B, 256]
           const float* __restrict__ b1,
           const float* __restrict__ g1,
           const float* __restrict__ be1,
           const float* __restrict__ b2,
           const float* __restrict__ g2,
           const float* __restrict__ be2,
           float* __restrict__ theta)         // [B, 512]
{
    __shared__ float xs[8 * OUTD];            // 16KB

    const int t = threadIdx.x;                 // 0..255
    const int row0 = blockIdx.x * 8;
    const int ox4 = (t & 127) * 4;             // 4 consecutive output cols
    const int ry = (t >> 7) * 4;               // row base {0, 4}
    const int w = t >> 5;                      // warp 0..7 (one LN row each)
    const int l = t & 31;

    // --- load mu tile [8,256] (512 float4 / 256 thr = 2 each) ---
    {
        const float4* src = (const float4*)(mu_in + (size_t)row0 * DD);
        float4* dst = (float4*)xs;
        dst[t]       = src[t];
        dst[t + 256] = src[t + 256];
    }
    __syncthreads();

    unsigned long long a01[4], a23[4];
    #pragma unroll
    for (int r = 0; r < 4; r++) { a01[r] = 0ull; a23[r] = 0ull; }

    // --- GEMM1: y1 = mu @ w1^T ---
    for (int k = 0; k < DD; k += 4) {
        float4 m[4];
        #pragma unroll
        for (int r = 0; r < 4; r++)
            m[r] = *(const float4*)(xs + (ry + r) * DD + k);
        #pragma unroll
        for (int kk = 0; kk < 4; kk++) {
            ulonglong2 wp = *(const ulonglong2*)(g_w1t + (size_t)(k + kk) * OUTD + ox4);
            #pragma unroll
            for (int r = 0; r < 4; r++) {
                float mv = (kk == 0) ? m[r].x : (kk == 1) ? m[r].y
                         : (kk == 2) ? m[r].z : m[r].w;
                unsigned long long d;
                DUP2(d, __float_as_uint(mv));
                FMA2(a01[r], wp.x, d);
                FMA2(a23[r], wp.y, d);
            }
        }
    }
    __syncthreads();

    // --- y1 + b1 into xs[8][512] ---
    {
        const float4 bb = *(const float4*)(b1 + ox4);
        #pragma unroll
        for (int r = 0; r < 4; r++) {
            unsigned u0, u1, u2, u3;
            UNPK2(u0, u1, a01[r]);
            UNPK2(u2, u3, a23[r]);
            *(float4*)(xs + (ry + r) * OUTD + ox4) =
                make_float4(__uint_as_float(u0) + bb.x, __uint_as_float(u1) + bb.y,
                            __uint_as_float(u2) + bb.z, __uint_as_float(u3) + bb.w);
        }
    }
    __syncthreads();

    // --- LN1 + exact GELU (warp w handles row w) ---
    {
        const int row = w;
        float s = 0.0f, sq = 0.0f;
        #pragma unroll
        for (int j = 0; j < 16; j++) {
            float v = xs[row * OUTD + l + 32 * j];
            s += v; sq += v * v;
        }
        #pragma unroll
        for (int o = 16; o > 0; o >>= 1) {
            s  += __shfl_xor_sync(0xFFFFFFFFu, s, o);
            sq += __shfl_xor_sync(0xFFFFFFFFu, sq, o);
        }
        const float mean = s * (1.0f / OUTD);
        const float var  = sq * (1.0f / OUTD) - mean * mean;
        const float rstd = rsqrtf(var + 1e-5f);
        #pragma unroll
        for (int j = 0; j < 16; j++) {
            const int idx = l + 32 * j;
            float v = xs[row * OUTD + idx];
            v = (v - mean) * rstd * g1[idx] + be1[idx];
            v = 0.5f * v * (1.0f + erff(v * 0.70710678118654752f));
            xs[row * OUTD + idx] = v;
        }
    }
    __syncthreads();

    // --- GEMM2: y2 = x @ w2^T ---
    #pragma unroll
    for (int r = 0; r < 4; r++) { a01[r] = 0ull; a23[r] = 0ull; }

    for (int k = 0; k < OUTD; k += 4) {
        float4 m[4];
        #pragma unroll
        for (int r = 0; r < 4; r++)
            m[r] = *(const float4*)(xs + (ry + r) * OUTD + k);
        #pragma unroll
        for (int kk = 0; kk < 4; kk++) {
            ulonglong2 wp = *(const ulonglong2*)(g_w2t + (size_t)(k + kk) * OUTD + ox4);
            #pragma unroll
            for (int r = 0; r < 4; r++) {
                float mv = (kk == 0) ? m[r].x : (kk == 1) ? m[r].y
                         : (kk == 2) ? m[r].z : m[r].w;
                unsigned long long d;
                DUP2(d, __float_as_uint(mv));
                FMA2(a01[r], wp.x, d);
                FMA2(a23[r], wp.y, d);
            }
        }
    }
    __syncthreads();

    // --- y2 + b2 ---
    {
        const float4 bb = *(const float4*)(b2 + ox4);
        #pragma unroll
        for (int r = 0; r < 4; r++) {
            unsigned u0, u1, u2, u3;
            UNPK2(u0, u1, a01[r]);
            UNPK2(u2, u3, a23[r]);
            *(float4*)(xs + (ry + r) * OUTD + ox4) =
                make_float4(__uint_as_float(u0) + bb.x, __uint_as_float(u1) + bb.y,
                            __uint_as_float(u2) + bb.z, __uint_as_float(u3) + bb.w);
        }
    }
    __syncthreads();

    // --- LN2 (warp w handles row w) ---
    {
        const int row = w;
        float s = 0.0f, sq = 0.0f;
        #pragma unroll
        for (int j = 0; j < 16; j++) {
            float v = xs[row * OUTD + l + 32 * j];
            s += v; sq += v * v;
        }
        #pragma unroll
        for (int o = 16; o > 0; o >>= 1) {
            s  += __shfl_xor_sync(0xFFFFFFFFu, s, o);
            sq += __shfl_xor_sync(0xFFFFFFFFu, sq, o);
        }
        const float mean = s * (1.0f / OUTD);
        const float var  = sq * (1.0f / OUTD) - mean * mean;
        const float rstd = rsqrtf(var + 1e-5f);
        #pragma unroll
        for (int j = 0; j < 16; j++) {
            const int idx = l + 32 * j;
            float v = xs[row * OUTD + idx];
            xs[row * OUTD + idx] = (v - mean) * rstd * g2[idx] + be2[idx];
        }
    }
    __syncthreads();

    // --- write theta tile (1024 float4 / 256 thr = 4 each) ---
    {
        float4* dst = (float4*)(theta + (size_t)row0 * OUTD);
        const float4* src = (const float4*)xs;
        #pragma unroll
        for (int i = 0; i < 4; i++)
            dst[t + 256 * i] = src[t + 256 * i];
    }
}

// ---------------------------------------------------------------------------
// Launch. Output layout: [theta (B*512) | alpha (B*64) | mu (B*256)]
// ---------------------------------------------------------------------------
extern "C" void kernel_launch(void* const* d_in, const int* in_sizes, int n_in,
                              void* d_out, int out_size)
{
    const float* h       = (const float*)d_in[0];
    const float* log_tau = (const float*)d_in[1];
    const float* w1      = (const float*)d_in[2];
    const float* b1      = (const float*)d_in[3];
    const float* g1      = (const float*)d_in[4];
    const float* be1     = (const float*)d_in[5];
    const float* w2      = (const float*)d_in[6];
    const float* b2      = (const float*)d_in[7];
    const float* g2      = (const float*)d_in[8];
    const float* be2     = (const float*)d_in[9];

    const int batch = in_sizes[0] / (NN * DD);

    float* out   = (float*)d_out;
    float* theta = out;
    float* alpha = out + (size_t)batch * OUTD;
    float* mu    = out + (size_t)batch * OUTD + (size_t)batch * NN;

    float* w1t_dev = nullptr;
    float* w2t_dev = nullptr;
    cudaGetSymbolAddress((void**)&w1t_dev, g_w1t);
    cudaGetSymbolAddress((void**)&w2t_dev, g_w2t);

    dim3 tb(32, 8);
    transpose_kernel<<<dim3(DD / 32, OUTD / 32), tb>>>(w1, w1t_dev, OUTD, DD);
    transpose_kernel<<<dim3(OUTD / 32, OUTD / 32), tb>>>(w2, w2t_dev, OUTD, OUTD);

    cluster_kernel<<<batch, 512>>>(h, log_tau, alpha, mu);
    mlp_kernel<<<batch / 8, 256>>>(mu, b1, g1, be1, b2, g2, be2, theta);
}